// round 1
// baseline (speedup 1.0000x reference)
#include <cuda_runtime.h>

#define Bb 4
#define Qq 512
#define Kk 1024
#define QSd 256
#define KSd 256
#define VDd 256
#define Hh 128
#define NEGV -1e9f

// Scratch (no allocations allowed): projected q/k and scores/attn buffer.
__device__ __align__(16) float g_qp[Bb * Qq * Hh];   // 1 MB
__device__ __align__(16) float g_kp[Bb * Kk * Hh];   // 2 MB
__device__ __align__(16) float g_sc[Bb * Qq * Kk];   // 8 MB

__device__ __forceinline__ float tanh_fast(float x) {
    float y;
    asm("tanh.approx.f32 %0, %1;" : "=f"(y) : "f"(x));
    return y;
}

// ---------------------------------------------------------------------------
// Projection: C[M,128] = A[M,256] @ W[256,128]. which=0 -> g_qp, 1 -> g_kp.
// Block: 256 threads, 16 rows. Thread: 1 col (tid&127), 8 rows (tid>>7 half).
// ---------------------------------------------------------------------------
__global__ void proj_kernel(const float* __restrict__ A,
                            const float* __restrict__ W,
                            int which) {
    __shared__ float a_s[16][256];   // 16 KB
    __shared__ float w_s[32][128];   // 16 KB
    float* C = which ? g_kp : g_qp;

    const int tid  = threadIdx.x;
    const int row0 = blockIdx.x * 16;

    // Load full A tile (16 x 256), coalesced.
    #pragma unroll
    for (int i = 0; i < 16; i++)
        a_s[i][tid] = A[(row0 + i) * 256 + tid];

    const int col = tid & 127;
    const int rg  = tid >> 7;   // 0 or 1 -> rows rg*8 .. rg*8+7
    float acc[8];
    #pragma unroll
    for (int i = 0; i < 8; i++) acc[i] = 0.f;

    for (int dc = 0; dc < 256; dc += 32) {
        __syncthreads();
        // Load W chunk (32 x 128), 16 elems/thread, coalesced.
        #pragma unroll
        for (int i = 0; i < 16; i++) {
            int idx = i * 256 + tid;
            w_s[idx >> 7][idx & 127] = W[(dc + (idx >> 7)) * 128 + (idx & 127)];
        }
        __syncthreads();
        #pragma unroll 8
        for (int d = 0; d < 32; d++) {
            float wv = w_s[d][col];
            #pragma unroll
            for (int i = 0; i < 8; i++)
                acc[i] += a_s[rg * 8 + i][dc + d] * wv;
        }
    }
    #pragma unroll
    for (int i = 0; i < 8; i++)
        C[(row0 + rg * 8 + i) * 128 + col] = acc[i];
}

// ---------------------------------------------------------------------------
// Scores: sc[b][q][k] = sum_h w[h] * tanh(qp[b][q][h] + kp[b][k][h]), masked.
// Block: 256 threads = 16x16, tile 32q x 32k, 2x2 micro-tile per thread.
// ---------------------------------------------------------------------------
__global__ void scores_kernel(const float* __restrict__ w_v,
                              const int* __restrict__ valid_lens) {
    __shared__ float qs[32 * 129];   // padded stride 129 -> conflict-free
    __shared__ float ks[32 * 129];
    __shared__ float ws[128];

    const int b  = blockIdx.z;
    const int q0 = blockIdx.y * 32;
    const int k0 = blockIdx.x * 32;
    const int tid = threadIdx.x;

    const float* qp = g_qp + (b * Qq + q0) * Hh;
    const float* kp = g_kp + (b * Kk + k0) * Hh;

    #pragma unroll
    for (int i = 0; i < 16; i++) {
        int idx = i * 256 + tid;          // 0..4095
        int r = idx >> 7, c = idx & 127;
        qs[r * 129 + c] = qp[r * 128 + c];
        ks[r * 129 + c] = kp[r * 128 + c];
    }
    if (tid < 128) ws[tid] = w_v[tid];
    __syncthreads();

    const int tx = tid & 15;   // k direction (2 consecutive cols)
    const int ty = tid >> 4;   // q direction (2 consecutive rows)
    const float* qa = qs + (2 * ty)     * 129;
    const float* qb = qs + (2 * ty + 1) * 129;
    const float* ka = ks + (2 * tx)     * 129;
    const float* kb = ks + (2 * tx + 1) * 129;

    float a00 = 0.f, a01 = 0.f, a10 = 0.f, a11 = 0.f;
    #pragma unroll 4
    for (int h = 0; h < 128; h++) {
        float w  = ws[h];
        float q0v = qa[h], q1v = qb[h];
        float k0v = ka[h], k1v = kb[h];
        a00 += w * tanh_fast(q0v + k0v);
        a01 += w * tanh_fast(q0v + k1v);
        a10 += w * tanh_fast(q1v + k0v);
        a11 += w * tanh_fast(q1v + k1v);
    }

    const int vl = valid_lens[b];
    const int kk = k0 + 2 * tx;
    if (kk     >= vl) { a00 = NEGV; a10 = NEGV; }
    if (kk + 1 >= vl) { a01 = NEGV; a11 = NEGV; }

    float2* o0 = (float2*)&g_sc[(b * Qq + q0 + 2 * ty)     * Kk + kk];
    float2* o1 = (float2*)&g_sc[(b * Qq + q0 + 2 * ty + 1) * Kk + kk];
    *o0 = make_float2(a00, a01);
    *o1 = make_float2(a10, a11);
}

// ---------------------------------------------------------------------------
// Softmax over K=1024 per (b,q) row, in place on g_sc. 256 thr, float4/thread.
// ---------------------------------------------------------------------------
__global__ void softmax_kernel() {
    const int row = blockIdx.x;          // b*Qq + q
    const int tid = threadIdx.x;
    float4* p = (float4*)&g_sc[row * Kk];
    float4 v = p[tid];

    __shared__ float redm[8];
    __shared__ float reds[8];
    const int wid = tid >> 5, lid = tid & 31;

    float m = fmaxf(fmaxf(v.x, v.y), fmaxf(v.z, v.w));
    #pragma unroll
    for (int o = 16; o; o >>= 1) m = fmaxf(m, __shfl_xor_sync(~0u, m, o));
    if (lid == 0) redm[wid] = m;
    __syncthreads();
    m = redm[0];
    #pragma unroll
    for (int i = 1; i < 8; i++) m = fmaxf(m, redm[i]);

    v.x = __expf(v.x - m);
    v.y = __expf(v.y - m);
    v.z = __expf(v.z - m);
    v.w = __expf(v.w - m);

    float s = v.x + v.y + v.z + v.w;
    #pragma unroll
    for (int o = 16; o; o >>= 1) s += __shfl_xor_sync(~0u, s, o);
    if (lid == 0) reds[wid] = s;
    __syncthreads();
    s = reds[0];
    #pragma unroll
    for (int i = 1; i < 8; i++) s += reds[i];

    float inv = __frcp_rn(s);
    v.x *= inv; v.y *= inv; v.z *= inv; v.w *= inv;
    p[tid] = v;
}

// ---------------------------------------------------------------------------
// AV: out[b][q][v] = sum_k attn[b][q][k] * values[b][k][v].
// Grid (VD/64, Q/16, B) = (4,32,4)=512 blocks, 256 thr.
// Thread: 1 q row x 4 v cols (float4). K staged in smem in chunks of 32.
// ---------------------------------------------------------------------------
__global__ void av_kernel(const float* __restrict__ values,
                          float* __restrict__ out) {
    __shared__ __align__(16) float at_s[16 * 32];   // attn tile 16q x 32k
    __shared__ __align__(16) float vs_s[32 * 64];   // values tile 32k x 64v

    const int b  = blockIdx.z;
    const int q0 = blockIdx.y * 16;
    const int v0 = blockIdx.x * 64;
    const int tid = threadIdx.x;
    const int vt = tid & 15;    // v group (4 cols)
    const int qi = tid >> 4;    // q row within tile

    const float* attn = g_sc + (b * Qq + q0) * Kk;
    const float* vals = values + (size_t)b * Kk * VDd + v0;

    float4 acc = make_float4(0.f, 0.f, 0.f, 0.f);

    for (int kc = 0; kc < Kk; kc += 32) {
        __syncthreads();
        // attn tile: 512 elems, 2/thread, coalesced.
        #pragma unroll
        for (int i = 0; i < 2; i++) {
            int e = i * 256 + tid;
            int r = e >> 5, c = e & 31;
            at_s[r * 32 + c] = attn[r * Kk + kc + c];
        }
        // values tile: 512 float4, 2/thread, coalesced.
        #pragma unroll
        for (int i = 0; i < 2; i++) {
            int e = i * 256 + tid;       // float4 index: row = e>>4, col4 = e&15
            int r = e >> 4, c = e & 15;
            ((float4*)vs_s)[e] = ((const float4*)(vals + (size_t)(kc + r) * VDd))[c];
        }
        __syncthreads();
        #pragma unroll 8
        for (int kkI = 0; kkI < 32; kkI++) {
            float a = at_s[qi * 32 + kkI];
            float4 vv = ((float4*)vs_s)[kkI * 16 + vt];
            acc.x += a * vv.x;
            acc.y += a * vv.y;
            acc.z += a * vv.z;
            acc.w += a * vv.w;
        }
    }

    float4* o = (float4*)(out + (size_t)(b * Qq + q0 + qi) * VDd + v0);
    o[vt] = acc;
}

// ---------------------------------------------------------------------------
extern "C" void kernel_launch(void* const* d_in, const int* in_sizes, int n_in,
                              void* d_out, int out_size) {
    const float* queries    = (const float*)d_in[0];
    const float* keys       = (const float*)d_in[1];
    const float* values     = (const float*)d_in[2];
    const int*   valid_lens = (const int*)  d_in[3];
    const float* W_q        = (const float*)d_in[4];
    const float* W_k        = (const float*)d_in[5];
    const float* w_v        = (const float*)d_in[6];
    float* out = (float*)d_out;

    // Projections: (B*Q,256)@(256,128) and (B*K,256)@(256,128)
    proj_kernel<<<(Bb * Qq) / 16, 256>>>(queries, W_q, 0);
    proj_kernel<<<(Bb * Kk) / 16, 256>>>(keys,    W_k, 1);

    // Scores + mask
    scores_kernel<<<dim3(Kk / 32, Qq / 32, Bb), 256>>>(w_v, valid_lens);

    // Softmax
    softmax_kernel<<<Bb * Qq, 256>>>();

    // attn @ values
    av_kernel<<<dim3(VDd / 64, Qq / 16, Bb), 256>>>(values, out);
}